// round 1
// baseline (speedup 1.0000x reference)
#include <cuda_runtime.h>
#include <math.h>

// Problem shape (fixed by the reference setup):
//   B=16, L=512, H=8, D=64, k = int(log(512)) = 6
// Key identity: mean over the full circular-correlation axis collapses the FFT:
//   sum_t irfft(conj(Q)*K)[t] = (sum_d q[d]) * (sum_d k[d])
// so x_corr_mean[b,l] = (1/(H*L)) * sum_h (sum_d q) * (sum_d k).

#define B_ 16
#define L_ 512
#define H_ 8
#define D_ 64
#define HD_ (H_ * D_)      // 512 floats per (b,l) row
#define K_TOP 6

__device__ float g_scores[B_ * L_];   // scratch, no allocation allowed

// ---------------------------------------------------------------------------
// Kernel 1: per-(b,l) score = (1/4096) * sum_h (sum_d q)(sum_d k)
// One block per row, 128 threads, float4 loads (512 floats q + 512 floats k).
// Thread t covers elements [4t, 4t+3]; head h = t/16 (16 threads per head).
// ---------------------------------------------------------------------------
__global__ __launch_bounds__(128) void score_kernel(
    const float* __restrict__ q, const float* __restrict__ k)
{
    const int bl = blockIdx.x;                  // 0..8191
    const int t  = threadIdx.x;                 // 0..127
    const float4* qp = reinterpret_cast<const float4*>(q + (size_t)bl * HD_);
    const float4* kp = reinterpret_cast<const float4*>(k + (size_t)bl * HD_);

    float4 q4 = qp[t];
    float4 k4 = kp[t];
    float qs = q4.x + q4.y + q4.z + q4.w;
    float ks = k4.x + k4.y + k4.z + k4.w;

    // Segmented reduction over 16-lane groups (one head per group).
    // Offsets <= 8 keep the 16-lane segments (starting at lane 0 / 16) intact.
    #pragma unroll
    for (int o = 8; o > 0; o >>= 1) {
        qs += __shfl_down_sync(0xFFFFFFFFu, qs, o);
        ks += __shfl_down_sync(0xFFFFFFFFu, ks, o);
    }

    __shared__ float sq[H_], sk[H_];
    if ((t & 15) == 0) {                        // lanes 0,16 of each warp
        int h = t >> 4;                          // head index 0..7
        sq[h] = qs;
        sk[h] = ks;
    }
    __syncthreads();

    if (t == 0) {
        float tot = 0.0f;
        #pragma unroll
        for (int h = 0; h < H_; h++)
            tot += sq[h] * sk[h];
        g_scores[bl] = tot * (1.0f / (H_ * L_));
    }
}

// ---------------------------------------------------------------------------
// Kernel 2: per-batch top-6 of 512 scores -> softmax -> weighted gather-sum
// of values rows. One block per batch, 512 threads. Output [B, H, D].
// ---------------------------------------------------------------------------
__global__ __launch_bounds__(512) void topk_agg_kernel(
    const float* __restrict__ values, float* __restrict__ out)
{
    const int b = blockIdx.x;       // 0..15
    const int t = threadIdx.x;      // 0..511

    __shared__ float sm[L_];        // master copy (entries knocked out per round)
    __shared__ float rv[L_];        // reduction values
    __shared__ int   ri[L_];        // reduction indices
    __shared__ float topv[K_TOP];
    __shared__ int   topi[K_TOP];
    __shared__ float w[K_TOP];

    sm[t] = g_scores[b * L_ + t];
    __syncthreads();

    // 6 rounds of argmax; tie-break toward lower index (matches jax.lax.top_k).
    for (int r = 0; r < K_TOP; r++) {
        rv[t] = sm[t];
        ri[t] = t;
        __syncthreads();
        #pragma unroll
        for (int s = 256; s > 0; s >>= 1) {
            if (t < s) {
                float v2 = rv[t + s]; int i2 = ri[t + s];
                if (v2 > rv[t] || (v2 == rv[t] && i2 < ri[t])) {
                    rv[t] = v2; ri[t] = i2;
                }
            }
            __syncthreads();
        }
        if (t == 0) {
            topv[r] = rv[0];
            topi[r] = ri[0];
            sm[ri[0]] = -INFINITY;
        }
        __syncthreads();
    }

    // Softmax of the 6 top values (topv[0] is the max).
    if (t == 0) {
        float m = topv[0];
        float s = 0.0f;
        #pragma unroll
        for (int i = 0; i < K_TOP; i++) { w[i] = __expf(topv[i] - m); s += w[i]; }
        float inv = 1.0f / s;
        #pragma unroll
        for (int i = 0; i < K_TOP; i++) w[i] *= inv;
    }
    __syncthreads();

    // Weighted sum of gathered values rows: out[b, t] = sum_i w[i]*V[b, idx_i, t]
    float acc = 0.0f;
    #pragma unroll
    for (int i = 0; i < K_TOP; i++) {
        const float* vp = values + ((size_t)b * L_ + topi[i]) * HD_;
        acc = fmaf(w[i], vp[t], acc);
    }
    out[(size_t)b * HD_ + t] = acc;
}

extern "C" void kernel_launch(void* const* d_in, const int* in_sizes, int n_in,
                              void* d_out, int out_size)
{
    const float* q = (const float*)d_in[0];
    const float* k = (const float*)d_in[1];
    const float* v = (const float*)d_in[2];
    float* out = (float*)d_out;

    score_kernel<<<B_ * L_, 128>>>(q, k);
    topk_agg_kernel<<<B_, L_>>>(v, out);
}

// round 3
// speedup vs baseline: 1.4706x; 1.4706x over previous
#include <cuda_runtime.h>
#include <math.h>

// Shape (fixed): B=16, L=512, H=8, D=64, k = int(log 512) = 6
// Identity: sum_t irfft(conj(Q)*K)[t] = (sum_d q)(sum_d k), so
// x_corr_mean[b,l] = (1/(H*L)) * sum_h (sum_d q[b,l,h,:]) (sum_d k[b,l,h,:]).

#define B_ 16
#define L_ 512
#define H_ 8
#define D_ 64
#define HD_ (H_ * D_)
#define K_TOP 6

__device__ float g_scores[B_ * L_];   // scratch (no allocation allowed)

// ---------------------------------------------------------------------------
// Kernel 1: score[b,l] = (1/4096) * sum_h (sum_d q)(sum_d k)
// One block per (b,l) row, 128 threads, float4 loads. HBM-bound (33.5 MB).
// ---------------------------------------------------------------------------
__global__ __launch_bounds__(128) void score_kernel(
    const float* __restrict__ q, const float* __restrict__ k)
{
    const int bl = blockIdx.x;
    const int t  = threadIdx.x;
    const float4* qp = reinterpret_cast<const float4*>(q + (size_t)bl * HD_);
    const float4* kp = reinterpret_cast<const float4*>(k + (size_t)bl * HD_);

    float4 q4 = qp[t];
    float4 k4 = kp[t];
    float qs = q4.x + q4.y + q4.z + q4.w;
    float ks = k4.x + k4.y + k4.z + k4.w;

    // Segmented 16-lane reduction (one head per 16-lane group).
    #pragma unroll
    for (int o = 8; o > 0; o >>= 1) {
        qs += __shfl_down_sync(0xFFFFFFFFu, qs, o);
        ks += __shfl_down_sync(0xFFFFFFFFu, ks, o);
    }

    __shared__ float sq[H_], sk[H_];
    if ((t & 15) == 0) {
        int h = t >> 4;
        sq[h] = qs;
        sk[h] = ks;
    }
    __syncthreads();

    if (t == 0) {
        float tot = 0.0f;
        #pragma unroll
        for (int h = 0; h < H_; h++)
            tot += sq[h] * sk[h];
        g_scores[bl] = tot * (1.0f / (H_ * L_));
    }
}

// ---------------------------------------------------------------------------
// Kernel 2: per-batch top-6 + softmax + weighted gather-sum.
// One block per batch (512 threads). Warp 0 does the ENTIRE top-k + softmax
// in registers with shuffles — no __syncthreads in the top-k loop.
// ---------------------------------------------------------------------------
__global__ __launch_bounds__(512) void topk_agg_kernel(
    const float* __restrict__ values, float* __restrict__ out)
{
    const int b = blockIdx.x;      // 0..15
    const int t = threadIdx.x;     // 0..511

    __shared__ float s_w[K_TOP];
    __shared__ int   s_idx[K_TOP];

    if (t < 32) {
        const int lane = t;
        // Lane holds scores[lane*16 .. lane*16+15] in registers.
        float v[16];
        const float* sp = g_scores + b * L_ + lane * 16;
        #pragma unroll
        for (int j = 0; j < 16; j++) v[j] = sp[j];

        float topv[K_TOP];
        int   topi[K_TOP];

        #pragma unroll
        for (int r = 0; r < K_TOP; r++) {
            // Local argmax over 16 (first-max wins -> lower index on tie).
            float bv = -INFINITY; int bi = 0;
            #pragma unroll
            for (int j = 0; j < 16; j++) {
                if (v[j] > bv) { bv = v[j]; bi = lane * 16 + j; }
            }
            // Warp argmax, tie-break toward lower index.
            #pragma unroll
            for (int o = 16; o > 0; o >>= 1) {
                float ov = __shfl_xor_sync(0xFFFFFFFFu, bv, o);
                int   oi = __shfl_xor_sync(0xFFFFFFFFu, bi, o);
                if (ov > bv || (ov == bv && oi < bi)) { bv = ov; bi = oi; }
            }
            topv[r] = bv;
            topi[r] = bi;
            // Knock the winner out of its owner lane.
            if ((bi >> 4) == lane) v[bi & 15] = -INFINITY;
        }

        // Softmax (topv[0] is the max) — computed redundantly per lane.
        float m = topv[0];
        float s = 0.0f;
        float w[K_TOP];
        #pragma unroll
        for (int i = 0; i < K_TOP; i++) { w[i] = __expf(topv[i] - m); s += w[i]; }
        float inv = 1.0f / s;
        if (lane < K_TOP) {
            s_w[lane]   = w[lane] * inv;
            s_idx[lane] = topi[lane];
        }
    }
    __syncthreads();

    // out[b, t] = sum_i w[i] * V[b, idx_i, t]
    float acc = 0.0f;
    #pragma unroll
    for (int i = 0; i < K_TOP; i++) {
        const float* vp = values + ((size_t)b * L_ + s_idx[i]) * HD_;
        acc = fmaf(s_w[i], vp[t], acc);
    }
    out[(size_t)b * HD_ + t] = acc;
}

extern "C" void kernel_launch(void* const* d_in, const int* in_sizes, int n_in,
                              void* d_out, int out_size)
{
    const float* q = (const float*)d_in[0];
    const float* k = (const float*)d_in[1];
    const float* v = (const float*)d_in[2];
    float* out = (float*)d_out;

    score_kernel<<<B_ * L_, 128>>>(q, k);
    topk_agg_kernel<<<B_, 512>>>(v, out);
}